// round 11
// baseline (speedup 1.0000x reference)
#include <cuda_runtime.h>
#include <math.h>

#define NN 100000
#define EE 1000000
#define F  64
#define F4 16          // float4 elements per row
#define C1 4
#define C2 3
#define ALPHA 0.1f
#define HPAD 68        // padded hs row (floats)

struct alignas(8) Edge { int s; float w; };

// ---------------- scratch (device globals, zero-initialized) ----------------
__device__ int   g_cnt[NN];       // invariant: zero at entry of every call
__device__ float g_dinv[NN];
__device__ int   g_rowptr[NN + 1];
__device__ int   g_cursor[NN];
__device__ Edge  g_edge[EE];
__device__ float g_xa[NN * F];
__device__ float g_xb[NN * F];

// ---------------- CSR build ----------------
__global__ void k_hist(const int* __restrict__ col) {
    int e = blockIdx.x * blockDim.x + threadIdx.x;
    if (e < EE) atomicAdd(&g_cnt[col[e]], 1);
}

// single-block exclusive scan over N=100000 counts; writes dinv, cursor,
// and RE-ZEROES g_cnt so the next kernel_launch call starts clean.
__global__ void k_scan() {
    __shared__ int sums[1024];
    int t = threadIdx.x;
    const int CH = (NN + 1023) / 1024;   // 98
    int beg = t * CH;
    int end = beg + CH; if (end > NN) end = NN;
    int s = 0;
    for (int i = beg; i < end; i++) s += g_cnt[i];
    sums[t] = s;
    __syncthreads();
    for (int off = 1; off < 1024; off <<= 1) {
        int v = (t >= off) ? sums[t - off] : 0;
        __syncthreads();
        sums[t] += v;
        __syncthreads();
    }
    int run = (t > 0) ? sums[t - 1] : 0;
    for (int i = beg; i < end; i++) {
        int c = g_cnt[i];
        g_rowptr[i] = run;
        g_cursor[i] = run;
        g_dinv[i]   = rsqrtf((float)c + 1.0f);  // +1 self-loop
        run += c;
        g_cnt[i] = 0;                           // restore invariant
    }
    if (t == 1023) g_rowptr[NN] = run;   // == EE
}

__global__ void k_scatter(const int* __restrict__ ei) {
    int e = blockIdx.x * blockDim.x + threadIdx.x;
    if (e < EE) {
        int s = ei[e];          // row (source)
        int d = ei[EE + e];     // col (target)
        int p = atomicAdd(&g_cursor[d], 1);
        Edge ed; ed.s = s; ed.w = g_dinv[s] * g_dinv[d];
        g_edge[p] = ed;
    }
}

// ---------------- gather: half-warp per node, float4 lanes, unroll 4 ------
__device__ __forceinline__ float4 gather_row(const float4* __restrict__ x4,
                                             int e, int end, int sub) {
    float4 acc = make_float4(0.f, 0.f, 0.f, 0.f);
    const int2* ep = (const int2*)g_edge;
    for (; e + 4 <= end; e += 4) {
        int2 r0 = __ldg(&ep[e]),     r1 = __ldg(&ep[e + 1]);
        int2 r2 = __ldg(&ep[e + 2]), r3 = __ldg(&ep[e + 3]);
        float4 v0 = __ldg(&x4[(size_t)r0.x * F4 + sub]);
        float4 v1 = __ldg(&x4[(size_t)r1.x * F4 + sub]);
        float4 v2 = __ldg(&x4[(size_t)r2.x * F4 + sub]);
        float4 v3 = __ldg(&x4[(size_t)r3.x * F4 + sub]);
        float w0 = __int_as_float(r0.y), w1 = __int_as_float(r1.y);
        float w2 = __int_as_float(r2.y), w3 = __int_as_float(r3.y);
        acc.x = fmaf(w0, v0.x, acc.x); acc.y = fmaf(w0, v0.y, acc.y);
        acc.z = fmaf(w0, v0.z, acc.z); acc.w = fmaf(w0, v0.w, acc.w);
        acc.x = fmaf(w1, v1.x, acc.x); acc.y = fmaf(w1, v1.y, acc.y);
        acc.z = fmaf(w1, v1.z, acc.z); acc.w = fmaf(w1, v1.w, acc.w);
        acc.x = fmaf(w2, v2.x, acc.x); acc.y = fmaf(w2, v2.y, acc.y);
        acc.z = fmaf(w2, v2.z, acc.z); acc.w = fmaf(w2, v2.w, acc.w);
        acc.x = fmaf(w3, v3.x, acc.x); acc.y = fmaf(w3, v3.y, acc.y);
        acc.z = fmaf(w3, v3.z, acc.z); acc.w = fmaf(w3, v3.w, acc.w);
    }
    for (; e < end; e++) {
        int2 r = __ldg(&ep[e]);
        float4 v = __ldg(&x4[(size_t)r.x * F4 + sub]);
        float w = __int_as_float(r.y);
        acc.x = fmaf(w, v.x, acc.x); acc.y = fmaf(w, v.y, acc.y);
        acc.z = fmaf(w, v.z, acc.z); acc.w = fmaf(w, v.w, acc.w);
    }
    return acc;
}

// ---------------- fused GCN2Conv layer: prop + residual + GEMM + relu ----
__global__ void __launch_bounds__(256)
k_layer(const float* __restrict__ x_in, float* __restrict__ x_out,
        const float* __restrict__ W) {
    __shared__ float4 Wsh[F * F4];   // [k][sub]
    __shared__ float  hs[16][HPAD];
    int t = threadIdx.x;
    const float4* W4 = (const float4*)W;
#pragma unroll
    for (int i = 0; i < 4; i++) Wsh[t + i * 256] = W4[t + i * 256];
    __syncthreads();

    int warp = t >> 5, lane = t & 31, half = lane >> 4, sub = lane & 15;
    int nb = warp * 2 + half;
    int n  = blockIdx.x * 16 + nb;           // grid*16 == NN exactly

    const float4* x4 = (const float4*)x_in;
    int eb = __ldg(&g_rowptr[n]), ee = __ldg(&g_rowptr[n + 1]);
    float4 acc = gather_row(x4, eb, ee, sub);

    float dn = g_dinv[n];
    float sn = dn * dn;                       // self-loop weight
    float4 xn = __ldg(&x4[(size_t)n * F4 + sub]);
    float4 h;
    h.x = (1.f - ALPHA) * (acc.x + sn * xn.x) + ALPHA * xn.x;
    h.y = (1.f - ALPHA) * (acc.y + sn * xn.y) + ALPHA * xn.y;
    h.z = (1.f - ALPHA) * (acc.z + sn * xn.z) + ALPHA * xn.z;
    h.w = (1.f - ALPHA) * (acc.w + sn * xn.w) + ALPHA * xn.w;
    ((float4*)&hs[nb][0])[sub] = h;
    __syncwarp(0xffffffffu);

    const float4* hrow = (const float4*)&hs[nb][0];
    float4 o = make_float4(0.f, 0.f, 0.f, 0.f);
#pragma unroll
    for (int j = 0; j < 16; j++) {
        float4 hv = hrow[j];
        float4 w0 = Wsh[(4 * j + 0) * F4 + sub];
        float4 w1 = Wsh[(4 * j + 1) * F4 + sub];
        float4 w2 = Wsh[(4 * j + 2) * F4 + sub];
        float4 w3 = Wsh[(4 * j + 3) * F4 + sub];
        o.x = fmaf(hv.x, w0.x, o.x); o.y = fmaf(hv.x, w0.y, o.y);
        o.z = fmaf(hv.x, w0.z, o.z); o.w = fmaf(hv.x, w0.w, o.w);
        o.x = fmaf(hv.y, w1.x, o.x); o.y = fmaf(hv.y, w1.y, o.y);
        o.z = fmaf(hv.y, w1.z, o.z); o.w = fmaf(hv.y, w1.w, o.w);
        o.x = fmaf(hv.z, w2.x, o.x); o.y = fmaf(hv.z, w2.y, o.y);
        o.z = fmaf(hv.z, w2.z, o.z); o.w = fmaf(hv.z, w2.w, o.w);
        o.x = fmaf(hv.w, w3.x, o.x); o.y = fmaf(hv.w, w3.y, o.y);
        o.z = fmaf(hv.w, w3.z, o.z); o.w = fmaf(hv.w, w3.w, o.w);
    }
    o.x = fmaxf(o.x, 0.f); o.y = fmaxf(o.y, 0.f);
    o.z = fmaxf(o.z, 0.f); o.w = fmaxf(o.w, 0.f);
    ((float4*)x_out)[(size_t)n * F4 + sub] = o;
}

// -------- last GCN2Conv layer fused with GCNConv GEMM: y = relu(...)@Wg ---
__global__ void __launch_bounds__(256)
k_layer_gcn(const float* __restrict__ x_in, float* __restrict__ y_out,
            const float* __restrict__ W, const float* __restrict__ Wg) {
    __shared__ float4 Wsh[F * F4];
    __shared__ float4 Wgs[F * F4];
    __shared__ float  hs[16][HPAD];
    __shared__ float  os[16][HPAD];
    int t = threadIdx.x;
    const float4* W4  = (const float4*)W;
    const float4* Wg4 = (const float4*)Wg;
#pragma unroll
    for (int i = 0; i < 4; i++) {
        Wsh[t + i * 256] = W4[t + i * 256];
        Wgs[t + i * 256] = Wg4[t + i * 256];
    }
    __syncthreads();

    int warp = t >> 5, lane = t & 31, half = lane >> 4, sub = lane & 15;
    int nb = warp * 2 + half;
    int n  = blockIdx.x * 16 + nb;

    const float4* x4 = (const float4*)x_in;
    int eb = __ldg(&g_rowptr[n]), ee = __ldg(&g_rowptr[n + 1]);
    float4 acc = gather_row(x4, eb, ee, sub);

    float dn = g_dinv[n];
    float sn = dn * dn;
    float4 xn = __ldg(&x4[(size_t)n * F4 + sub]);
    float4 h;
    h.x = (1.f - ALPHA) * (acc.x + sn * xn.x) + ALPHA * xn.x;
    h.y = (1.f - ALPHA) * (acc.y + sn * xn.y) + ALPHA * xn.y;
    h.z = (1.f - ALPHA) * (acc.z + sn * xn.z) + ALPHA * xn.z;
    h.w = (1.f - ALPHA) * (acc.w + sn * xn.w) + ALPHA * xn.w;
    ((float4*)&hs[nb][0])[sub] = h;
    __syncwarp(0xffffffffu);

    const float4* hrow = (const float4*)&hs[nb][0];
    float4 o = make_float4(0.f, 0.f, 0.f, 0.f);
#pragma unroll
    for (int j = 0; j < 16; j++) {
        float4 hv = hrow[j];
        float4 w0 = Wsh[(4 * j + 0) * F4 + sub];
        float4 w1 = Wsh[(4 * j + 1) * F4 + sub];
        float4 w2 = Wsh[(4 * j + 2) * F4 + sub];
        float4 w3 = Wsh[(4 * j + 3) * F4 + sub];
        o.x = fmaf(hv.x, w0.x, o.x); o.y = fmaf(hv.x, w0.y, o.y);
        o.z = fmaf(hv.x, w0.z, o.z); o.w = fmaf(hv.x, w0.w, o.w);
        o.x = fmaf(hv.y, w1.x, o.x); o.y = fmaf(hv.y, w1.y, o.y);
        o.z = fmaf(hv.y, w1.z, o.z); o.w = fmaf(hv.y, w1.w, o.w);
        o.x = fmaf(hv.z, w2.x, o.x); o.y = fmaf(hv.z, w2.y, o.y);
        o.z = fmaf(hv.z, w2.z, o.z); o.w = fmaf(hv.z, w2.w, o.w);
        o.x = fmaf(hv.w, w3.x, o.x); o.y = fmaf(hv.w, w3.y, o.y);
        o.z = fmaf(hv.w, w3.z, o.z); o.w = fmaf(hv.w, w3.w, o.w);
    }
    o.x = fmaxf(o.x, 0.f); o.y = fmaxf(o.y, 0.f);
    o.z = fmaxf(o.z, 0.f); o.w = fmaxf(o.w, 0.f);

    // second GEMM: y = relu_row @ Wg
    ((float4*)&os[nb][0])[sub] = o;
    __syncwarp(0xffffffffu);
    const float4* orow = (const float4*)&os[nb][0];
    float4 y = make_float4(0.f, 0.f, 0.f, 0.f);
#pragma unroll
    for (int j = 0; j < 16; j++) {
        float4 hv = orow[j];
        float4 w0 = Wgs[(4 * j + 0) * F4 + sub];
        float4 w1 = Wgs[(4 * j + 1) * F4 + sub];
        float4 w2 = Wgs[(4 * j + 2) * F4 + sub];
        float4 w3 = Wgs[(4 * j + 3) * F4 + sub];
        y.x = fmaf(hv.x, w0.x, y.x); y.y = fmaf(hv.x, w0.y, y.y);
        y.z = fmaf(hv.x, w0.z, y.z); y.w = fmaf(hv.x, w0.w, y.w);
        y.x = fmaf(hv.y, w1.x, y.x); y.y = fmaf(hv.y, w1.y, y.y);
        y.z = fmaf(hv.y, w1.z, y.z); y.w = fmaf(hv.y, w1.w, y.w);
        y.x = fmaf(hv.z, w2.x, y.x); y.y = fmaf(hv.z, w2.y, y.y);
        y.z = fmaf(hv.z, w2.z, y.z); y.w = fmaf(hv.z, w2.w, y.w);
        y.x = fmaf(hv.w, w3.x, y.x); y.y = fmaf(hv.w, w3.y, y.y);
        y.z = fmaf(hv.w, w3.z, y.z); y.w = fmaf(hv.w, w3.w, y.w);
    }
    ((float4*)y_out)[(size_t)n * F4 + sub] = y;
}

// ---------------- final: h = prop(y)+b_gcn ; out1 = h@W1+b1 ; out2 = h@W2+b2
__global__ void __launch_bounds__(256)
k_final(const float* __restrict__ y, float* __restrict__ out,
        const float* __restrict__ W1, const float* __restrict__ b1,
        const float* __restrict__ W2, const float* __restrict__ b2,
        const float* __restrict__ bg) {
    __shared__ float W1s[F * C1];
    __shared__ float W2s[F * C2];
    __shared__ float bgs[F];
    int t = threadIdx.x;
    if (t < F * C1) W1s[t] = W1[t];
    if (t < F * C2) W2s[t] = W2[t];
    if (t < F)      bgs[t] = bg[t];
    __syncthreads();

    int warp = t >> 5, lane = t & 31, half = lane >> 4, sub = lane & 15;
    int nb = warp * 2 + half;
    int n  = blockIdx.x * 16 + nb;

    const float4* y4 = (const float4*)y;
    int eb = __ldg(&g_rowptr[n]), ee = __ldg(&g_rowptr[n + 1]);
    float4 acc = gather_row(y4, eb, ee, sub);

    float dn = g_dinv[n];
    float sn = dn * dn;
    float4 yn = __ldg(&y4[(size_t)n * F4 + sub]);
    float4 h;
    h.x = acc.x + sn * yn.x + bgs[4 * sub + 0];
    h.y = acc.y + sn * yn.y + bgs[4 * sub + 1];
    h.z = acc.z + sn * yn.z + bgs[4 * sub + 2];
    h.w = acc.w + sn * yn.w + bgs[4 * sub + 3];

    // write h (third output block)
    float* out_h = out + (size_t)NN * (C1 + C2);
    ((float4*)out_h)[(size_t)n * F4 + sub] = h;

    // heads: per-lane partials over its 4 features, reduce across 16 lanes
    float p[C1 + C2];
#pragma unroll
    for (int c = 0; c < C1; c++)
        p[c] = h.x * W1s[(4 * sub + 0) * C1 + c] + h.y * W1s[(4 * sub + 1) * C1 + c]
             + h.z * W1s[(4 * sub + 2) * C1 + c] + h.w * W1s[(4 * sub + 3) * C1 + c];
#pragma unroll
    for (int c = 0; c < C2; c++)
        p[C1 + c] = h.x * W2s[(4 * sub + 0) * C2 + c] + h.y * W2s[(4 * sub + 1) * C2 + c]
                  + h.z * W2s[(4 * sub + 2) * C2 + c] + h.w * W2s[(4 * sub + 3) * C2 + c];
#pragma unroll
    for (int off = 8; off; off >>= 1) {
#pragma unroll
        for (int c = 0; c < C1 + C2; c++)
            p[c] += __shfl_down_sync(0xffffffffu, p[c], off, 16);
    }
    if (sub == 0) {
#pragma unroll
        for (int c = 0; c < C1; c++)
            out[(size_t)n * C1 + c] = p[c] + __ldg(&b1[c]);
        float* o2 = out + (size_t)NN * C1;
#pragma unroll
        for (int c = 0; c < C2; c++)
            o2[(size_t)n * C2 + c] = p[C1 + c] + __ldg(&b2[c]);
    }
}

// ---------------- launch ----------------
extern "C" void kernel_launch(void* const* d_in, const int* in_sizes, int n_in,
                              void* d_out, int out_size) {
    const float* x   = (const float*)d_in[0];
    const int*   ei  = (const int*)  d_in[1];
    const float* Ws  = (const float*)d_in[2];
    const float* Wg  = (const float*)d_in[3];
    const float* bg  = (const float*)d_in[4];
    const float* W1  = (const float*)d_in[5];
    const float* b1  = (const float*)d_in[6];
    const float* W2  = (const float*)d_in[7];
    const float* b2  = (const float*)d_in[8];
    float* out = (float*)d_out;

    float *xa, *xb;
    cudaGetSymbolAddress((void**)&xa, g_xa);
    cudaGetSymbolAddress((void**)&xb, g_xb);

    k_hist<<<(EE + 255) / 256, 256>>>(ei + EE);       // launch 0
    k_scan<<<1, 1024>>>();                            // launch 1 (also re-zeroes cnt)
    k_scatter<<<(EE + 255) / 256, 256>>>(ei);         // launch 2

    int gb = NN / 16;                                 // 6250, exact
    k_layer    <<<gb, 256>>>(x,  xa, Ws);             // launch 3  <- ncu capture lands here
    k_layer    <<<gb, 256>>>(xa, xb, Ws + F * F);     // launch 4
    k_layer_gcn<<<gb, 256>>>(xb, xa, Ws + 2 * F * F, Wg);
    k_final    <<<gb, 256>>>(xa, out, W1, b1, W2, b2, bg);
}

// round 15
// speedup vs baseline: 1.2169x; 1.2169x over previous
#include <cuda_runtime.h>
#include <math.h>

#define NN 100000
#define EE 1000000
#define F  64
#define F4 16          // float4 elements per row
#define C1 4
#define C2 3
#define ALPHA 0.1f
#define HPAD 68        // padded hs row (floats); 272B rows, 16B aligned
#define NPB 80         // nodes per block in layer kernels
#define RND 5          // gather rounds per warp (NPB/16)

struct alignas(8) Edge { int s; float w; };

// ---------------- scratch (device globals, zero-initialized) ----------------
__device__ int   g_cnt[NN];       // invariant: zero at entry of every call
__device__ float g_dinv[NN];
__device__ int   g_rowptr[NN + 1];
__device__ int   g_cursor[NN];
__device__ Edge  g_edge[EE];
__device__ float g_xa[NN * F];
__device__ float g_xb[NN * F];

// ---------------- CSR build ----------------
__global__ void k_hist(const int* __restrict__ col) {
    int e = blockIdx.x * blockDim.x + threadIdx.x;
    if (e < EE) atomicAdd(&g_cnt[col[e]], 1);
}

// single-block scan; writes rowptr/dinv/cursor, re-zeroes g_cnt.
__global__ void k_scan() {
    __shared__ int sums[1024];
    int t = threadIdx.x;
    const int CH = (NN + 1023) / 1024;   // 98
    int beg = t * CH;
    int end = beg + CH; if (end > NN) end = NN;
    int s = 0;
    for (int i = beg; i < end; i++) s += g_cnt[i];
    sums[t] = s;
    __syncthreads();
    for (int off = 1; off < 1024; off <<= 1) {
        int v = (t >= off) ? sums[t - off] : 0;
        __syncthreads();
        sums[t] += v;
        __syncthreads();
    }
    int run = (t > 0) ? sums[t - 1] : 0;
    for (int i = beg; i < end; i++) {
        int c = g_cnt[i];
        g_rowptr[i] = run;
        g_cursor[i] = run;
        g_dinv[i]   = rsqrtf((float)c + 1.0f);  // +1 self-loop
        run += c;
        g_cnt[i] = 0;                           // restore invariant
    }
    if (t == 1023) g_rowptr[NN] = run;   // == EE
}

__global__ void k_scatter(const int* __restrict__ ei) {
    int e = blockIdx.x * blockDim.x + threadIdx.x;
    if (e < EE) {
        int s = ei[e];          // row (source)
        int d = ei[EE + e];     // col (target)
        int p = atomicAdd(&g_cursor[d], 1);
        Edge ed; ed.s = s; ed.w = g_dinv[s] * g_dinv[d];
        g_edge[p] = ed;
    }
}

// ---------------- gather: half-warp per node, float4 lanes, unroll 8 ------
__device__ __forceinline__ float4 gather_row(const float4* __restrict__ x4,
                                             int e, int end, int sub) {
    float4 acc = make_float4(0.f, 0.f, 0.f, 0.f);
    const int2* ep = (const int2*)g_edge;
    for (; e + 8 <= end; e += 8) {
        int2 r[8];
        float4 v[8];
#pragma unroll
        for (int j = 0; j < 8; j++) r[j] = __ldg(&ep[e + j]);
#pragma unroll
        for (int j = 0; j < 8; j++)
            v[j] = __ldg(&x4[(size_t)r[j].x * F4 + sub]);
#pragma unroll
        for (int j = 0; j < 8; j++) {
            float w = __int_as_float(r[j].y);
            acc.x = fmaf(w, v[j].x, acc.x); acc.y = fmaf(w, v[j].y, acc.y);
            acc.z = fmaf(w, v[j].z, acc.z); acc.w = fmaf(w, v[j].w, acc.w);
        }
    }
    if (e + 4 <= end) {
        int2 r[4];
        float4 v[4];
#pragma unroll
        for (int j = 0; j < 4; j++) r[j] = __ldg(&ep[e + j]);
#pragma unroll
        for (int j = 0; j < 4; j++)
            v[j] = __ldg(&x4[(size_t)r[j].x * F4 + sub]);
#pragma unroll
        for (int j = 0; j < 4; j++) {
            float w = __int_as_float(r[j].y);
            acc.x = fmaf(w, v[j].x, acc.x); acc.y = fmaf(w, v[j].y, acc.y);
            acc.z = fmaf(w, v[j].z, acc.z); acc.w = fmaf(w, v[j].w, acc.w);
        }
        e += 4;
    }
    for (; e < end; e++) {
        int2 r = __ldg(&ep[e]);
        float4 v = __ldg(&x4[(size_t)r.x * F4 + sub]);
        float w = __int_as_float(r.y);
        acc.x = fmaf(w, v.x, acc.x); acc.y = fmaf(w, v.y, acc.y);
        acc.z = fmaf(w, v.z, acc.z); acc.w = fmaf(w, v.w, acc.w);
    }
    return acc;
}

// compute h = (1-a)*(acc + sn*xn) + a*xn and store to hs row
__device__ __forceinline__ void store_h(float* hrow, int sub, float4 acc,
                                        float4 xn, float sn) {
    float4 h;
    h.x = (1.f - ALPHA) * (acc.x + sn * xn.x) + ALPHA * xn.x;
    h.y = (1.f - ALPHA) * (acc.y + sn * xn.y) + ALPHA * xn.y;
    h.z = (1.f - ALPHA) * (acc.z + sn * xn.z) + ALPHA * xn.z;
    h.w = (1.f - ALPHA) * (acc.w + sn * xn.w) + ALPHA * xn.w;
    ((float4*)hrow)[sub] = h;
}

// ---------------- fused GCN2Conv layer: prop + residual + GEMM + relu ----
__global__ void __launch_bounds__(256)
k_layer(const float* __restrict__ x_in, float* __restrict__ x_out,
        const float* __restrict__ W) {
    __shared__ float4 Wsh[F * F4];   // [k][sub], 16 KB
    __shared__ float  hs[NPB][HPAD]; // 21.8 KB
    int t = threadIdx.x;
    const float4* W4 = (const float4*)W;
#pragma unroll
    for (int i = 0; i < 4; i++) Wsh[t + i * 256] = W4[t + i * 256];
    __syncthreads();

    int warp = t >> 5, lane = t & 31, half = lane >> 4, sub = lane & 15;
    int nb = warp * 2 + half;
    int nbase = blockIdx.x * NPB;            // grid*NPB == NN exactly

    const float4* x4 = (const float4*)x_in;
#pragma unroll
    for (int r = 0; r < RND; r++) {
        int n = nbase + r * 16 + nb;
        int eb = __ldg(&g_rowptr[n]), ee = __ldg(&g_rowptr[n + 1]);
        float4 acc = gather_row(x4, eb, ee, sub);
        float dn = g_dinv[n];
        float4 xn = __ldg(&x4[(size_t)n * F4 + sub]);
        store_h(&hs[r * 16 + nb][0], sub, acc, xn, dn * dn);
    }
    __syncwarp(0xffffffffu);

    float4 o[RND];
#pragma unroll
    for (int r = 0; r < RND; r++) o[r] = make_float4(0.f, 0.f, 0.f, 0.f);
#pragma unroll
    for (int j = 0; j < 16; j++) {
        float4 w0 = Wsh[(4 * j + 0) * F4 + sub];
        float4 w1 = Wsh[(4 * j + 1) * F4 + sub];
        float4 w2 = Wsh[(4 * j + 2) * F4 + sub];
        float4 w3 = Wsh[(4 * j + 3) * F4 + sub];
#pragma unroll
        for (int r = 0; r < RND; r++) {
            float4 hv = ((const float4*)&hs[r * 16 + nb][0])[j];
            o[r].x = fmaf(hv.x, w0.x, o[r].x); o[r].y = fmaf(hv.x, w0.y, o[r].y);
            o[r].z = fmaf(hv.x, w0.z, o[r].z); o[r].w = fmaf(hv.x, w0.w, o[r].w);
            o[r].x = fmaf(hv.y, w1.x, o[r].x); o[r].y = fmaf(hv.y, w1.y, o[r].y);
            o[r].z = fmaf(hv.y, w1.z, o[r].z); o[r].w = fmaf(hv.y, w1.w, o[r].w);
            o[r].x = fmaf(hv.z, w2.x, o[r].x); o[r].y = fmaf(hv.z, w2.y, o[r].y);
            o[r].z = fmaf(hv.z, w2.z, o[r].z); o[r].w = fmaf(hv.z, w2.w, o[r].w);
            o[r].x = fmaf(hv.w, w3.x, o[r].x); o[r].y = fmaf(hv.w, w3.y, o[r].y);
            o[r].z = fmaf(hv.w, w3.z, o[r].z); o[r].w = fmaf(hv.w, w3.w, o[r].w);
        }
    }
#pragma unroll
    for (int r = 0; r < RND; r++) {
        int n = nbase + r * 16 + nb;
        float4 v;
        v.x = fmaxf(o[r].x, 0.f); v.y = fmaxf(o[r].y, 0.f);
        v.z = fmaxf(o[r].z, 0.f); v.w = fmaxf(o[r].w, 0.f);
        ((float4*)x_out)[(size_t)n * F4 + sub] = v;
    }
}

// -------- last GCN2Conv layer fused with GCNConv GEMM: y = relu(...)@Wg ---
__global__ void __launch_bounds__(256)
k_layer_gcn(const float* __restrict__ x_in, float* __restrict__ y_out,
            const float* __restrict__ W, const float* __restrict__ Wg) {
    __shared__ float4 Wsh[F * F4];   // reused for W then Wg
    __shared__ float  hs[NPB][HPAD];
    int t = threadIdx.x;
    const float4* W4  = (const float4*)W;
    const float4* Wg4 = (const float4*)Wg;
#pragma unroll
    for (int i = 0; i < 4; i++) Wsh[t + i * 256] = W4[t + i * 256];
    __syncthreads();

    int warp = t >> 5, lane = t & 31, half = lane >> 4, sub = lane & 15;
    int nb = warp * 2 + half;
    int nbase = blockIdx.x * NPB;

    const float4* x4 = (const float4*)x_in;
#pragma unroll
    for (int r = 0; r < RND; r++) {
        int n = nbase + r * 16 + nb;
        int eb = __ldg(&g_rowptr[n]), ee = __ldg(&g_rowptr[n + 1]);
        float4 acc = gather_row(x4, eb, ee, sub);
        float dn = g_dinv[n];
        float4 xn = __ldg(&x4[(size_t)n * F4 + sub]);
        store_h(&hs[r * 16 + nb][0], sub, acc, xn, dn * dn);
    }
    __syncwarp(0xffffffffu);

    float4 o[RND];
#pragma unroll
    for (int r = 0; r < RND; r++) o[r] = make_float4(0.f, 0.f, 0.f, 0.f);
#pragma unroll
    for (int j = 0; j < 16; j++) {
        float4 w0 = Wsh[(4 * j + 0) * F4 + sub];
        float4 w1 = Wsh[(4 * j + 1) * F4 + sub];
        float4 w2 = Wsh[(4 * j + 2) * F4 + sub];
        float4 w3 = Wsh[(4 * j + 3) * F4 + sub];
#pragma unroll
        for (int r = 0; r < RND; r++) {
            float4 hv = ((const float4*)&hs[r * 16 + nb][0])[j];
            o[r].x = fmaf(hv.x, w0.x, o[r].x); o[r].y = fmaf(hv.x, w0.y, o[r].y);
            o[r].z = fmaf(hv.x, w0.z, o[r].z); o[r].w = fmaf(hv.x, w0.w, o[r].w);
            o[r].x = fmaf(hv.y, w1.x, o[r].x); o[r].y = fmaf(hv.y, w1.y, o[r].y);
            o[r].z = fmaf(hv.y, w1.z, o[r].z); o[r].w = fmaf(hv.y, w1.w, o[r].w);
            o[r].x = fmaf(hv.z, w2.x, o[r].x); o[r].y = fmaf(hv.z, w2.y, o[r].y);
            o[r].z = fmaf(hv.z, w2.z, o[r].z); o[r].w = fmaf(hv.z, w2.w, o[r].w);
            o[r].x = fmaf(hv.w, w3.x, o[r].x); o[r].y = fmaf(hv.w, w3.y, o[r].y);
            o[r].z = fmaf(hv.w, w3.z, o[r].z); o[r].w = fmaf(hv.w, w3.w, o[r].w);
        }
    }
    // relu, stash o back into hs; swap Wsh -> Wg; second GEMM
    __syncthreads();                          // everyone done reading Wsh & hs
#pragma unroll
    for (int r = 0; r < RND; r++) {
        float4 v;
        v.x = fmaxf(o[r].x, 0.f); v.y = fmaxf(o[r].y, 0.f);
        v.z = fmaxf(o[r].z, 0.f); v.w = fmaxf(o[r].w, 0.f);
        ((float4*)&hs[r * 16 + nb][0])[sub] = v;
    }
#pragma unroll
    for (int i = 0; i < 4; i++) Wsh[t + i * 256] = Wg4[t + i * 256];
    __syncthreads();

    float4 y[RND];
#pragma unroll
    for (int r = 0; r < RND; r++) y[r] = make_float4(0.f, 0.f, 0.f, 0.f);
#pragma unroll
    for (int j = 0; j < 16; j++) {
        float4 w0 = Wsh[(4 * j + 0) * F4 + sub];
        float4 w1 = Wsh[(4 * j + 1) * F4 + sub];
        float4 w2 = Wsh[(4 * j + 2) * F4 + sub];
        float4 w3 = Wsh[(4 * j + 3) * F4 + sub];
#pragma unroll
        for (int r = 0; r < RND; r++) {
            float4 hv = ((const float4*)&hs[r * 16 + nb][0])[j];
            y[r].x = fmaf(hv.x, w0.x, y[r].x); y[r].y = fmaf(hv.x, w0.y, y[r].y);
            y[r].z = fmaf(hv.x, w0.z, y[r].z); y[r].w = fmaf(hv.x, w0.w, y[r].w);
            y[r].x = fmaf(hv.y, w1.x, y[r].x); y[r].y = fmaf(hv.y, w1.y, y[r].y);
            y[r].z = fmaf(hv.y, w1.z, y[r].z); y[r].w = fmaf(hv.y, w1.w, y[r].w);
            y[r].x = fmaf(hv.z, w2.x, y[r].x); y[r].y = fmaf(hv.z, w2.y, y[r].y);
            y[r].z = fmaf(hv.z, w2.z, y[r].z); y[r].w = fmaf(hv.z, w2.w, y[r].w);
            y[r].x = fmaf(hv.w, w3.x, y[r].x); y[r].y = fmaf(hv.w, w3.y, y[r].y);
            y[r].z = fmaf(hv.w, w3.z, y[r].z); y[r].w = fmaf(hv.w, w3.w, y[r].w);
        }
    }
#pragma unroll
    for (int r = 0; r < RND; r++) {
        int n = nbase + r * 16 + nb;
        ((float4*)y_out)[(size_t)n * F4 + sub] = y[r];
    }
}

// ---------------- final: h = prop(y)+b_gcn ; out1 = h@W1+b1 ; out2 = h@W2+b2
__global__ void __launch_bounds__(256)
k_final(const float* __restrict__ y, float* __restrict__ out,
        const float* __restrict__ W1, const float* __restrict__ b1,
        const float* __restrict__ W2, const float* __restrict__ b2,
        const float* __restrict__ bg) {
    __shared__ float W1s[F * C1];
    __shared__ float W2s[F * C2];
    __shared__ float bgs[F];
    int t = threadIdx.x;
    if (t < F * C1) W1s[t] = W1[t];
    if (t < F * C2) W2s[t] = W2[t];
    if (t < F)      bgs[t] = bg[t];
    __syncthreads();

    int warp = t >> 5, lane = t & 31, half = lane >> 4, sub = lane & 15;
    int nb = warp * 2 + half;
    int n  = blockIdx.x * 16 + nb;

    const float4* y4 = (const float4*)y;
    int eb = __ldg(&g_rowptr[n]), ee = __ldg(&g_rowptr[n + 1]);
    float4 acc = gather_row(y4, eb, ee, sub);

    float dn = g_dinv[n];
    float sn = dn * dn;
    float4 yn = __ldg(&y4[(size_t)n * F4 + sub]);
    float4 h;
    h.x = acc.x + sn * yn.x + bgs[4 * sub + 0];
    h.y = acc.y + sn * yn.y + bgs[4 * sub + 1];
    h.z = acc.z + sn * yn.z + bgs[4 * sub + 2];
    h.w = acc.w + sn * yn.w + bgs[4 * sub + 3];

    // write h (third output block)
    float* out_h = out + (size_t)NN * (C1 + C2);
    ((float4*)out_h)[(size_t)n * F4 + sub] = h;

    // heads: per-lane partials over its 4 features, reduce across 16 lanes
    float p[C1 + C2];
#pragma unroll
    for (int c = 0; c < C1; c++)
        p[c] = h.x * W1s[(4 * sub + 0) * C1 + c] + h.y * W1s[(4 * sub + 1) * C1 + c]
             + h.z * W1s[(4 * sub + 2) * C1 + c] + h.w * W1s[(4 * sub + 3) * C1 + c];
#pragma unroll
    for (int c = 0; c < C2; c++)
        p[C1 + c] = h.x * W2s[(4 * sub + 0) * C2 + c] + h.y * W2s[(4 * sub + 1) * C2 + c]
                  + h.z * W2s[(4 * sub + 2) * C2 + c] + h.w * W2s[(4 * sub + 3) * C2 + c];
#pragma unroll
    for (int off = 8; off; off >>= 1) {
#pragma unroll
        for (int c = 0; c < C1 + C2; c++)
            p[c] += __shfl_down_sync(0xffffffffu, p[c], off, 16);
    }
    if (sub == 0) {
#pragma unroll
        for (int c = 0; c < C1; c++)
            out[(size_t)n * C1 + c] = p[c] + __ldg(&b1[c]);
        float* o2 = out + (size_t)NN * C1;
#pragma unroll
        for (int c = 0; c < C2; c++)
            o2[(size_t)n * C2 + c] = p[C1 + c] + __ldg(&b2[c]);
    }
}

// ---------------- launch ----------------
extern "C" void kernel_launch(void* const* d_in, const int* in_sizes, int n_in,
                              void* d_out, int out_size) {
    const float* x   = (const float*)d_in[0];
    const int*   ei  = (const int*)  d_in[1];
    const float* Ws  = (const float*)d_in[2];
    const float* Wg  = (const float*)d_in[3];
    const float* bg  = (const float*)d_in[4];
    const float* W1  = (const float*)d_in[5];
    const float* b1  = (const float*)d_in[6];
    const float* W2  = (const float*)d_in[7];
    const float* b2  = (const float*)d_in[8];
    float* out = (float*)d_out;

    float *xa, *xb;
    cudaGetSymbolAddress((void**)&xa, g_xa);
    cudaGetSymbolAddress((void**)&xb, g_xb);

    k_hist<<<(EE + 255) / 256, 256>>>(ei + EE);       // launch 0
    k_scan<<<1, 1024>>>();                            // launch 1 (re-zeroes cnt)
    k_scatter<<<(EE + 255) / 256, 256>>>(ei);         // launch 2

    int gb = NN / NPB;                                // 1250, exact
    k_layer    <<<gb, 256>>>(x,  xa, Ws);             // launch 3  <- ncu lands here
    k_layer    <<<gb, 256>>>(xa, xb, Ws + F * F);     // launch 4
    k_layer_gcn<<<gb, 256>>>(xb, xa, Ws + 2 * F * F, Wg);
    k_final    <<<NN / 16, 256>>>(xa, out, W1, b1, W2, b2, bg);
}

// round 16
// speedup vs baseline: 1.8945x; 1.5568x over previous
#include <cuda_runtime.h>
#include <math.h>

#define NN 100000
#define EE 1000000
#define F  64
#define F4 16          // float4 elements per row
#define C1 4
#define C2 3
#define ALPHA 0.1f
#define HPAD 64        // hs row stride (floats); 256B rows, conflict-free (see notes)
#define NPB 80         // nodes per block in layer kernels
#define RND 5          // gather rounds per warp (NPB/16)

struct alignas(8) Edge { int s; float w; };

// ---------------- scratch (device globals, zero-initialized) ----------------
__device__ __align__(16) int   g_cnt[NN];     // invariant: zero at entry
__device__ __align__(16) float g_dinv[NN];
__device__ __align__(16) int   g_rowptr[NN + 4];
__device__ __align__(16) int   g_cursor[NN];
__device__ Edge  g_edge[EE];
__device__ float g_xa[NN * F];
__device__ float g_xb[NN * F];

// ---------------- CSR build (4 edges per thread, int4 loads) ----------------
__global__ void k_hist(const int* __restrict__ col) {
    int i = blockIdx.x * blockDim.x + threadIdx.x;
    if (i < EE / 4) {
        int4 c = __ldg(&((const int4*)col)[i]);
        atomicAdd(&g_cnt[c.x], 1);
        atomicAdd(&g_cnt[c.y], 1);
        atomicAdd(&g_cnt[c.z], 1);
        atomicAdd(&g_cnt[c.w], 1);
    }
}

// single-block scan: 1000 threads x 100-elem chunks, vectorized IO.
// writes rowptr/dinv/cursor, re-zeroes g_cnt.
__global__ void k_scan() {
    __shared__ int sums[1024];
    int t = threadIdx.x;
    const int4* c4 = (const int4*)g_cnt;
    int base = t * 25;               // int4 index; chunk = 100 ints
    int s = 0;
    if (t < 1000) {
#pragma unroll
        for (int i = 0; i < 25; i++) {
            int4 c = __ldg(&c4[base + i]);
            s += c.x + c.y + c.z + c.w;
        }
    }
    sums[t] = s;
    __syncthreads();
    for (int off = 1; off < 1024; off <<= 1) {
        int v = (t >= off) ? sums[t - off] : 0;
        __syncthreads();
        sums[t] += v;
        __syncthreads();
    }
    int run = (t > 0) ? sums[t - 1] : 0;
    if (t < 1000) {
        int4*   rp4 = (int4*)g_rowptr;
        int4*   cu4 = (int4*)g_cursor;
        float4* dv4 = (float4*)g_dinv;
        int4*   cn4 = (int4*)g_cnt;
        const int4 zero4 = make_int4(0, 0, 0, 0);
#pragma unroll
        for (int i = 0; i < 25; i++) {
            int4 c = __ldg(&c4[base + i]);
            int4 rp;
            rp.x = run;
            rp.y = rp.x + c.x;
            rp.z = rp.y + c.y;
            rp.w = rp.z + c.z;
            run  = rp.w + c.w;
            rp4[base + i] = rp;
            cu4[base + i] = rp;
            float4 dv;
            dv.x = rsqrtf((float)c.x + 1.0f);
            dv.y = rsqrtf((float)c.y + 1.0f);
            dv.z = rsqrtf((float)c.z + 1.0f);
            dv.w = rsqrtf((float)c.w + 1.0f);
            dv4[base + i] = dv;
            cn4[base + i] = zero4;   // restore invariant
        }
    }
    if (t == 0) g_rowptr[NN] = EE;
}

__global__ void k_scatter(const int* __restrict__ ei) {
    int i = blockIdx.x * blockDim.x + threadIdx.x;
    if (i < EE / 4) {
        int4 s4 = __ldg(&((const int4*)ei)[i]);
        int4 d4 = __ldg(&((const int4*)(ei + EE))[i]);
        int p;
        Edge ed;
        p = atomicAdd(&g_cursor[d4.x], 1);
        ed.s = s4.x; ed.w = g_dinv[s4.x] * g_dinv[d4.x]; g_edge[p] = ed;
        p = atomicAdd(&g_cursor[d4.y], 1);
        ed.s = s4.y; ed.w = g_dinv[s4.y] * g_dinv[d4.y]; g_edge[p] = ed;
        p = atomicAdd(&g_cursor[d4.z], 1);
        ed.s = s4.z; ed.w = g_dinv[s4.z] * g_dinv[d4.z]; g_edge[p] = ed;
        p = atomicAdd(&g_cursor[d4.w], 1);
        ed.s = s4.w; ed.w = g_dinv[s4.w] * g_dinv[d4.w]; g_edge[p] = ed;
    }
}

// ---------------- gather: half-warp per node, float4 lanes, unroll 8 ------
__device__ __forceinline__ float4 gather_row(const float4* __restrict__ x4,
                                             int e, int end, int sub) {
    float4 acc = make_float4(0.f, 0.f, 0.f, 0.f);
    const int2* ep = (const int2*)g_edge;
    for (; e + 8 <= end; e += 8) {
        float  w[8];
        float4 v[8];
#pragma unroll
        for (int j = 0; j < 8; j++) {
            int2 r = __ldg(&ep[e + j]);
            v[j] = __ldg(&x4[(size_t)r.x * F4 + sub]);
            w[j] = __int_as_float(r.y);
        }
#pragma unroll
        for (int j = 0; j < 8; j++) {
            acc.x = fmaf(w[j], v[j].x, acc.x); acc.y = fmaf(w[j], v[j].y, acc.y);
            acc.z = fmaf(w[j], v[j].z, acc.z); acc.w = fmaf(w[j], v[j].w, acc.w);
        }
    }
    if (e + 4 <= end) {
        float  w[4];
        float4 v[4];
#pragma unroll
        for (int j = 0; j < 4; j++) {
            int2 r = __ldg(&ep[e + j]);
            v[j] = __ldg(&x4[(size_t)r.x * F4 + sub]);
            w[j] = __int_as_float(r.y);
        }
#pragma unroll
        for (int j = 0; j < 4; j++) {
            acc.x = fmaf(w[j], v[j].x, acc.x); acc.y = fmaf(w[j], v[j].y, acc.y);
            acc.z = fmaf(w[j], v[j].z, acc.z); acc.w = fmaf(w[j], v[j].w, acc.w);
        }
        e += 4;
    }
    for (; e < end; e++) {
        int2 r = __ldg(&ep[e]);
        float4 v = __ldg(&x4[(size_t)r.x * F4 + sub]);
        float w = __int_as_float(r.y);
        acc.x = fmaf(w, v.x, acc.x); acc.y = fmaf(w, v.y, acc.y);
        acc.z = fmaf(w, v.z, acc.z); acc.w = fmaf(w, v.w, acc.w);
    }
    return acc;
}

// compute h = (1-a)*(acc + sn*xn) + a*xn and store to hs row
__device__ __forceinline__ void store_h(float* hrow, int sub, float4 acc,
                                        float4 xn, float sn) {
    float4 h;
    h.x = (1.f - ALPHA) * (acc.x + sn * xn.x) + ALPHA * xn.x;
    h.y = (1.f - ALPHA) * (acc.y + sn * xn.y) + ALPHA * xn.y;
    h.z = (1.f - ALPHA) * (acc.z + sn * xn.z) + ALPHA * xn.z;
    h.w = (1.f - ALPHA) * (acc.w + sn * xn.w) + ALPHA * xn.w;
    ((float4*)hrow)[sub] = h;
}

// ---------------- fused GCN2Conv layer: prop + residual + GEMM + relu ----
__global__ void __launch_bounds__(256)
k_layer(const float* __restrict__ x_in, float* __restrict__ x_out,
        const float* __restrict__ W) {
    __shared__ float4 Wsh[F * F4];   // 16 KB
    __shared__ float  hs[NPB][HPAD]; // 20.5 KB
    int t = threadIdx.x;
    const float4* W4 = (const float4*)W;
#pragma unroll
    for (int i = 0; i < 4; i++) Wsh[t + i * 256] = W4[t + i * 256];
    __syncthreads();

    int warp = t >> 5, lane = t & 31, half = lane >> 4, sub = lane & 15;
    int nb = warp * 2 + half;
    int nbase = blockIdx.x * NPB;            // grid*NPB == NN exactly

    const float4* x4 = (const float4*)x_in;
#pragma unroll
    for (int r = 0; r < RND; r++) {
        int n = nbase + r * 16 + nb;
        int eb = __ldg(&g_rowptr[n]), ee = __ldg(&g_rowptr[n + 1]);
        float4 acc = gather_row(x4, eb, ee, sub);
        float dn = g_dinv[n];
        float4 xn = __ldg(&x4[(size_t)n * F4 + sub]);
        store_h(&hs[r * 16 + nb][0], sub, acc, xn, dn * dn);
    }
    __syncwarp(0xffffffffu);

    float4 o[RND];
#pragma unroll
    for (int r = 0; r < RND; r++) o[r] = make_float4(0.f, 0.f, 0.f, 0.f);
#pragma unroll
    for (int j = 0; j < 16; j++) {
        float4 w0 = Wsh[(4 * j + 0) * F4 + sub];
        float4 w1 = Wsh[(4 * j + 1) * F4 + sub];
        float4 w2 = Wsh[(4 * j + 2) * F4 + sub];
        float4 w3 = Wsh[(4 * j + 3) * F4 + sub];
#pragma unroll
        for (int r = 0; r < RND; r++) {
            float4 hv = ((const float4*)&hs[r * 16 + nb][0])[j];
            o[r].x = fmaf(hv.x, w0.x, o[r].x); o[r].y = fmaf(hv.x, w0.y, o[r].y);
            o[r].z = fmaf(hv.x, w0.z, o[r].z); o[r].w = fmaf(hv.x, w0.w, o[r].w);
            o[r].x = fmaf(hv.y, w1.x, o[r].x); o[r].y = fmaf(hv.y, w1.y, o[r].y);
            o[r].z = fmaf(hv.y, w1.z, o[r].z); o[r].w = fmaf(hv.y, w1.w, o[r].w);
            o[r].x = fmaf(hv.z, w2.x, o[r].x); o[r].y = fmaf(hv.z, w2.y, o[r].y);
            o[r].z = fmaf(hv.z, w2.z, o[r].z); o[r].w = fmaf(hv.z, w2.w, o[r].w);
            o[r].x = fmaf(hv.w, w3.x, o[r].x); o[r].y = fmaf(hv.w, w3.y, o[r].y);
            o[r].z = fmaf(hv.w, w3.z, o[r].z); o[r].w = fmaf(hv.w, w3.w, o[r].w);
        }
    }
#pragma unroll
    for (int r = 0; r < RND; r++) {
        int n = nbase + r * 16 + nb;
        float4 v;
        v.x = fmaxf(o[r].x, 0.f); v.y = fmaxf(o[r].y, 0.f);
        v.z = fmaxf(o[r].z, 0.f); v.w = fmaxf(o[r].w, 0.f);
        ((float4*)x_out)[(size_t)n * F4 + sub] = v;
    }
}

// -------- last GCN2Conv layer fused with GCNConv GEMM: y = relu(...)@Wg ---
__global__ void __launch_bounds__(256)
k_layer_gcn(const float* __restrict__ x_in, float* __restrict__ y_out,
            const float* __restrict__ W, const float* __restrict__ Wg) {
    __shared__ float4 Wsh[F * F4];   // reused for W then Wg
    __shared__ float  hs[NPB][HPAD];
    int t = threadIdx.x;
    const float4* W4  = (const float4*)W;
    const float4* Wg4 = (const float4*)Wg;
#pragma unroll
    for (int i = 0; i < 4; i++) Wsh[t + i * 256] = W4[t + i * 256];
    __syncthreads();

    int warp = t >> 5, lane = t & 31, half = lane >> 4, sub = lane & 15;
    int nb = warp * 2 + half;
    int nbase = blockIdx.x * NPB;

    const float4* x4 = (const float4*)x_in;
#pragma unroll
    for (int r = 0; r < RND; r++) {
        int n = nbase + r * 16 + nb;
        int eb = __ldg(&g_rowptr[n]), ee = __ldg(&g_rowptr[n + 1]);
        float4 acc = gather_row(x4, eb, ee, sub);
        float dn = g_dinv[n];
        float4 xn = __ldg(&x4[(size_t)n * F4 + sub]);
        store_h(&hs[r * 16 + nb][0], sub, acc, xn, dn * dn);
    }
    __syncwarp(0xffffffffu);

    float4 o[RND];
#pragma unroll
    for (int r = 0; r < RND; r++) o[r] = make_float4(0.f, 0.f, 0.f, 0.f);
#pragma unroll
    for (int j = 0; j < 16; j++) {
        float4 w0 = Wsh[(4 * j + 0) * F4 + sub];
        float4 w1 = Wsh[(4 * j + 1) * F4 + sub];
        float4 w2 = Wsh[(4 * j + 2) * F4 + sub];
        float4 w3 = Wsh[(4 * j + 3) * F4 + sub];
#pragma unroll
        for (int r = 0; r < RND; r++) {
            float4 hv = ((const float4*)&hs[r * 16 + nb][0])[j];
            o[r].x = fmaf(hv.x, w0.x, o[r].x); o[r].y = fmaf(hv.x, w0.y, o[r].y);
            o[r].z = fmaf(hv.x, w0.z, o[r].z); o[r].w = fmaf(hv.x, w0.w, o[r].w);
            o[r].x = fmaf(hv.y, w1.x, o[r].x); o[r].y = fmaf(hv.y, w1.y, o[r].y);
            o[r].z = fmaf(hv.y, w1.z, o[r].z); o[r].w = fmaf(hv.y, w1.w, o[r].w);
            o[r].x = fmaf(hv.z, w2.x, o[r].x); o[r].y = fmaf(hv.z, w2.y, o[r].y);
            o[r].z = fmaf(hv.z, w2.z, o[r].z); o[r].w = fmaf(hv.z, w2.w, o[r].w);
            o[r].x = fmaf(hv.w, w3.x, o[r].x); o[r].y = fmaf(hv.w, w3.y, o[r].y);
            o[r].z = fmaf(hv.w, w3.z, o[r].z); o[r].w = fmaf(hv.w, w3.w, o[r].w);
        }
    }
    // relu, stash o back into hs; swap Wsh -> Wg; second GEMM
    __syncthreads();                          // everyone done reading Wsh & hs
#pragma unroll
    for (int r = 0; r < RND; r++) {
        float4 v;
        v.x = fmaxf(o[r].x, 0.f); v.y = fmaxf(o[r].y, 0.f);
        v.z = fmaxf(o[r].z, 0.f); v.w = fmaxf(o[r].w, 0.f);
        ((float4*)&hs[r * 16 + nb][0])[sub] = v;
    }
#pragma unroll
    for (int i = 0; i < 4; i++) Wsh[t + i * 256] = Wg4[t + i * 256];
    __syncthreads();

    float4 y[RND];
#pragma unroll
    for (int r = 0; r < RND; r++) y[r] = make_float4(0.f, 0.f, 0.f, 0.f);
#pragma unroll
    for (int j = 0; j < 16; j++) {
        float4 w0 = Wsh[(4 * j + 0) * F4 + sub];
        float4 w1 = Wsh[(4 * j + 1) * F4 + sub];
        float4 w2 = Wsh[(4 * j + 2) * F4 + sub];
        float4 w3 = Wsh[(4 * j + 3) * F4 + sub];
#pragma unroll
        for (int r = 0; r < RND; r++) {
            float4 hv = ((const float4*)&hs[r * 16 + nb][0])[j];
            y[r].x = fmaf(hv.x, w0.x, y[r].x); y[r].y = fmaf(hv.x, w0.y, y[r].y);
            y[r].z = fmaf(hv.x, w0.z, y[r].z); y[r].w = fmaf(hv.x, w0.w, y[r].w);
            y[r].x = fmaf(hv.y, w1.x, y[r].x); y[r].y = fmaf(hv.y, w1.y, y[r].y);
            y[r].z = fmaf(hv.y, w1.z, y[r].z); y[r].w = fmaf(hv.y, w1.w, y[r].w);
            y[r].x = fmaf(hv.z, w2.x, y[r].x); y[r].y = fmaf(hv.z, w2.y, y[r].y);
            y[r].z = fmaf(hv.z, w2.z, y[r].z); y[r].w = fmaf(hv.z, w2.w, y[r].w);
            y[r].x = fmaf(hv.w, w3.x, y[r].x); y[r].y = fmaf(hv.w, w3.y, y[r].y);
            y[r].z = fmaf(hv.w, w3.z, y[r].z); y[r].w = fmaf(hv.w, w3.w, y[r].w);
        }
    }
#pragma unroll
    for (int r = 0; r < RND; r++) {
        int n = nbase + r * 16 + nb;
        ((float4*)y_out)[(size_t)n * F4 + sub] = y[r];
    }
}

// ---------------- final: h = prop(y)+b_gcn ; out1 = h@W1+b1 ; out2 = h@W2+b2
__global__ void __launch_bounds__(256)
k_final(const float* __restrict__ y, float* __restrict__ out,
        const float* __restrict__ W1, const float* __restrict__ b1,
        const float* __restrict__ W2, const float* __restrict__ b2,
        const float* __restrict__ bg) {
    __shared__ float W1s[F * C1];
    __shared__ float W2s[F * C2];
    __shared__ float bgs[F];
    int t = threadIdx.x;
    if (t < F * C1) W1s[t] = W1[t];
    if (t < F * C2) W2s[t] = W2[t];
    if (t < F)      bgs[t] = bg[t];
    __syncthreads();

    int warp = t >> 5, lane = t & 31, half = lane >> 4, sub = lane & 15;
    int nb = warp * 2 + half;
    int n  = blockIdx.x * 16 + nb;

    const float4* y4 = (const float4*)y;
    int eb = __ldg(&g_rowptr[n]), ee = __ldg(&g_rowptr[n + 1]);
    float4 acc = gather_row(y4, eb, ee, sub);

    float dn = g_dinv[n];
    float sn = dn * dn;
    float4 yn = __ldg(&y4[(size_t)n * F4 + sub]);
    float4 h;
    h.x = acc.x + sn * yn.x + bgs[4 * sub + 0];
    h.y = acc.y + sn * yn.y + bgs[4 * sub + 1];
    h.z = acc.z + sn * yn.z + bgs[4 * sub + 2];
    h.w = acc.w + sn * yn.w + bgs[4 * sub + 3];

    // write h (third output block)
    float* out_h = out + (size_t)NN * (C1 + C2);
    ((float4*)out_h)[(size_t)n * F4 + sub] = h;

    // heads: per-lane partials over its 4 features, reduce across 16 lanes
    float p[C1 + C2];
#pragma unroll
    for (int c = 0; c < C1; c++)
        p[c] = h.x * W1s[(4 * sub + 0) * C1 + c] + h.y * W1s[(4 * sub + 1) * C1 + c]
             + h.z * W1s[(4 * sub + 2) * C1 + c] + h.w * W1s[(4 * sub + 3) * C1 + c];
#pragma unroll
    for (int c = 0; c < C2; c++)
        p[C1 + c] = h.x * W2s[(4 * sub + 0) * C2 + c] + h.y * W2s[(4 * sub + 1) * C2 + c]
                  + h.z * W2s[(4 * sub + 2) * C2 + c] + h.w * W2s[(4 * sub + 3) * C2 + c];
#pragma unroll
    for (int off = 8; off; off >>= 1) {
#pragma unroll
        for (int c = 0; c < C1 + C2; c++)
            p[c] += __shfl_down_sync(0xffffffffu, p[c], off, 16);
    }
    if (sub == 0) {
#pragma unroll
        for (int c = 0; c < C1; c++)
            out[(size_t)n * C1 + c] = p[c] + __ldg(&b1[c]);
        float* o2 = out + (size_t)NN * C1;
#pragma unroll
        for (int c = 0; c < C2; c++)
            o2[(size_t)n * C2 + c] = p[C1 + c] + __ldg(&b2[c]);
    }
}

// ---------------- launch ----------------
extern "C" void kernel_launch(void* const* d_in, const int* in_sizes, int n_in,
                              void* d_out, int out_size) {
    const float* x   = (const float*)d_in[0];
    const int*   ei  = (const int*)  d_in[1];
    const float* Ws  = (const float*)d_in[2];
    const float* Wg  = (const float*)d_in[3];
    const float* bg  = (const float*)d_in[4];
    const float* W1  = (const float*)d_in[5];
    const float* b1  = (const float*)d_in[6];
    const float* W2  = (const float*)d_in[7];
    const float* b2  = (const float*)d_in[8];
    float* out = (float*)d_out;

    float *xa, *xb;
    cudaGetSymbolAddress((void**)&xa, g_xa);
    cudaGetSymbolAddress((void**)&xb, g_xb);

    int ebq = (EE / 4 + 255) / 256;                   // 977
    k_hist<<<ebq, 256>>>(ei + EE);                    // launch 0
    k_scan<<<1, 1024>>>();                            // launch 1 (re-zeroes cnt)
    k_scatter<<<ebq, 256>>>(ei);                      // launch 2

    int gb = NN / NPB;                                // 1250, exact
    k_layer    <<<gb, 256>>>(x,  xa, Ws);             // launch 3  <- ncu lands here
    k_layer    <<<gb, 256>>>(xa, xb, Ws + F * F);     // launch 4
    k_layer_gcn<<<gb, 256>>>(xb, xa, Ws + 2 * F * F, Wg);
    k_final    <<<NN / 16, 256>>>(xa, out, W1, b1, W2, b2, bg);
}

// round 17
// speedup vs baseline: 1.9454x; 1.0268x over previous
#include <cuda_runtime.h>
#include <math.h>

#define NN 100000
#define EE 1000000
#define F  64
#define F4 16          // float4 elements per row
#define C1 4
#define C2 3
#define ALPHA 0.1f
#define HPAD 64        // hs row stride (floats); 256B rows
#define NPB 80         // nodes per block in layer kernels
#define RND 5          // gather rounds per warp (NPB/16)
#define GU  6          // gather unroll (predicated)

struct alignas(8) Edge { int s; float w; };

// ---------------- scratch (device globals, zero-initialized) ----------------
__device__ __align__(16) int   g_cnt[NN];     // invariant: zero at entry
__device__ __align__(16) float g_dinv[NN];
__device__ __align__(16) int   g_rowptr[NN + 4];
__device__ __align__(16) int   g_cursor[NN];
__device__ Edge  g_edge[EE];
__device__ float g_xa[NN * F];
__device__ float g_xb[NN * F];

// ---------------- CSR build (4 edges per thread, int4 loads) ----------------
__global__ void k_hist(const int* __restrict__ col) {
    int i = blockIdx.x * blockDim.x + threadIdx.x;
    if (i < EE / 4) {
        int4 c = __ldg(&((const int4*)col)[i]);
        atomicAdd(&g_cnt[c.x], 1);
        atomicAdd(&g_cnt[c.y], 1);
        atomicAdd(&g_cnt[c.z], 1);
        atomicAdd(&g_cnt[c.w], 1);
    }
}

// single-block scan: 1000 threads x 100-elem chunks, vectorized IO.
// writes rowptr/dinv/cursor, re-zeroes g_cnt.
__global__ void k_scan() {
    __shared__ int sums[1024];
    int t = threadIdx.x;
    const int4* c4 = (const int4*)g_cnt;
    int base = t * 25;               // int4 index; chunk = 100 ints
    int s = 0;
    if (t < 1000) {
#pragma unroll
        for (int i = 0; i < 25; i++) {
            int4 c = __ldg(&c4[base + i]);
            s += c.x + c.y + c.z + c.w;
        }
    }
    sums[t] = s;
    __syncthreads();
    for (int off = 1; off < 1024; off <<= 1) {
        int v = (t >= off) ? sums[t - off] : 0;
        __syncthreads();
        sums[t] += v;
        __syncthreads();
    }
    int run = (t > 0) ? sums[t - 1] : 0;
    if (t < 1000) {
        int4*   rp4 = (int4*)g_rowptr;
        int4*   cu4 = (int4*)g_cursor;
        float4* dv4 = (float4*)g_dinv;
        int4*   cn4 = (int4*)g_cnt;
        const int4 zero4 = make_int4(0, 0, 0, 0);
#pragma unroll
        for (int i = 0; i < 25; i++) {
            int4 c = __ldg(&c4[base + i]);
            int4 rp;
            rp.x = run;
            rp.y = rp.x + c.x;
            rp.z = rp.y + c.y;
            rp.w = rp.z + c.z;
            run  = rp.w + c.w;
            rp4[base + i] = rp;
            cu4[base + i] = rp;
            float4 dv;
            dv.x = rsqrtf((float)c.x + 1.0f);
            dv.y = rsqrtf((float)c.y + 1.0f);
            dv.z = rsqrtf((float)c.z + 1.0f);
            dv.w = rsqrtf((float)c.w + 1.0f);
            dv4[base + i] = dv;
            cn4[base + i] = zero4;   // restore invariant
        }
    }
    if (t == 0) g_rowptr[NN] = EE;
}

__global__ void k_scatter(const int* __restrict__ ei) {
    int i = blockIdx.x * blockDim.x + threadIdx.x;
    if (i < EE / 4) {
        int4 s4 = __ldg(&((const int4*)ei)[i]);
        int4 d4 = __ldg(&((const int4*)(ei + EE))[i]);
        int p;
        Edge ed;
        p = atomicAdd(&g_cursor[d4.x], 1);
        ed.s = s4.x; ed.w = g_dinv[s4.x] * g_dinv[d4.x]; g_edge[p] = ed;
        p = atomicAdd(&g_cursor[d4.y], 1);
        ed.s = s4.y; ed.w = g_dinv[s4.y] * g_dinv[d4.y]; g_edge[p] = ed;
        p = atomicAdd(&g_cursor[d4.z], 1);
        ed.s = s4.z; ed.w = g_dinv[s4.z] * g_dinv[d4.z]; g_edge[p] = ed;
        p = atomicAdd(&g_cursor[d4.w], 1);
        ed.s = s4.w; ed.w = g_dinv[s4.w] * g_dinv[d4.w]; g_edge[p] = ed;
    }
}

// ------- gather: half-warp per node, predicated unroll-6, no serial tail ---
__device__ __forceinline__ float4 gather_row(const float4* __restrict__ x4,
                                             int e, int end, int sub) {
    float4 acc = make_float4(0.f, 0.f, 0.f, 0.f);
    const int2* ep = (const int2*)g_edge;
    int last = end - 1;
    for (; e < end; e += GU) {
        float  w[GU];
        float4 v[GU];
#pragma unroll
        for (int j = 0; j < GU; j++) {
            int  idx = e + j;
            bool ok  = idx < end;
            idx = ok ? idx : last;          // clamp: in-bounds, line just used
            int2 r = __ldg(&ep[idx]);
            w[j] = ok ? __int_as_float(r.y) : 0.f;
            v[j] = __ldg(&x4[(size_t)r.x * F4 + sub]);
        }
#pragma unroll
        for (int j = 0; j < GU; j++) {
            acc.x = fmaf(w[j], v[j].x, acc.x); acc.y = fmaf(w[j], v[j].y, acc.y);
            acc.z = fmaf(w[j], v[j].z, acc.z); acc.w = fmaf(w[j], v[j].w, acc.w);
        }
    }
    return acc;
}

// compute h = (1-a)*(acc + sn*xn) + a*xn and store to hs row
__device__ __forceinline__ void store_h(float* hrow, int sub, float4 acc,
                                        float4 xn, float sn) {
    float4 h;
    h.x = (1.f - ALPHA) * (acc.x + sn * xn.x) + ALPHA * xn.x;
    h.y = (1.f - ALPHA) * (acc.y + sn * xn.y) + ALPHA * xn.y;
    h.z = (1.f - ALPHA) * (acc.z + sn * xn.z) + ALPHA * xn.z;
    h.w = (1.f - ALPHA) * (acc.w + sn * xn.w) + ALPHA * xn.w;
    ((float4*)hrow)[sub] = h;
}

// ---------------- fused GCN2Conv layer: prop + residual + GEMM + relu ----
__global__ void __launch_bounds__(256, 5)
k_layer(const float* __restrict__ x_in, float* __restrict__ x_out,
        const float* __restrict__ W) {
    __shared__ float4 Wsh[F * F4];   // 16 KB
    __shared__ float  hs[NPB][HPAD]; // 20.5 KB
    int t = threadIdx.x;
    const float4* W4 = (const float4*)W;
#pragma unroll
    for (int i = 0; i < 4; i++) Wsh[t + i * 256] = W4[t + i * 256];
    __syncthreads();

    int warp = t >> 5, lane = t & 31, half = lane >> 4, sub = lane & 15;
    int nb = warp * 2 + half;
    int nbase = blockIdx.x * NPB;            // grid*NPB == NN exactly

    const float4* x4 = (const float4*)x_in;
#pragma unroll
    for (int r = 0; r < RND; r++) {
        int n = nbase + r * 16 + nb;
        int eb = __ldg(&g_rowptr[n]), ee = __ldg(&g_rowptr[n + 1]);
        float4 acc = gather_row(x4, eb, ee, sub);
        float dn = g_dinv[n];
        float4 xn = __ldg(&x4[(size_t)n * F4 + sub]);
        store_h(&hs[r * 16 + nb][0], sub, acc, xn, dn * dn);
    }
    __syncwarp(0xffffffffu);

    float4 o[RND];
#pragma unroll
    for (int r = 0; r < RND; r++) o[r] = make_float4(0.f, 0.f, 0.f, 0.f);
#pragma unroll
    for (int j = 0; j < 16; j++) {
        float4 w0 = Wsh[(4 * j + 0) * F4 + sub];
        float4 w1 = Wsh[(4 * j + 1) * F4 + sub];
        float4 w2 = Wsh[(4 * j + 2) * F4 + sub];
        float4 w3 = Wsh[(4 * j + 3) * F4 + sub];
#pragma unroll
        for (int r = 0; r < RND; r++) {
            float4 hv = ((const float4*)&hs[r * 16 + nb][0])[j];
            o[r].x = fmaf(hv.x, w0.x, o[r].x); o[r].y = fmaf(hv.x, w0.y, o[r].y);
            o[r].z = fmaf(hv.x, w0.z, o[r].z); o[r].w = fmaf(hv.x, w0.w, o[r].w);
            o[r].x = fmaf(hv.y, w1.x, o[r].x); o[r].y = fmaf(hv.y, w1.y, o[r].y);
            o[r].z = fmaf(hv.y, w1.z, o[r].z); o[r].w = fmaf(hv.y, w1.w, o[r].w);
            o[r].x = fmaf(hv.z, w2.x, o[r].x); o[r].y = fmaf(hv.z, w2.y, o[r].y);
            o[r].z = fmaf(hv.z, w2.z, o[r].z); o[r].w = fmaf(hv.z, w2.w, o[r].w);
            o[r].x = fmaf(hv.w, w3.x, o[r].x); o[r].y = fmaf(hv.w, w3.y, o[r].y);
            o[r].z = fmaf(hv.w, w3.z, o[r].z); o[r].w = fmaf(hv.w, w3.w, o[r].w);
        }
    }
#pragma unroll
    for (int r = 0; r < RND; r++) {
        int n = nbase + r * 16 + nb;
        float4 v;
        v.x = fmaxf(o[r].x, 0.f); v.y = fmaxf(o[r].y, 0.f);
        v.z = fmaxf(o[r].z, 0.f); v.w = fmaxf(o[r].w, 0.f);
        ((float4*)x_out)[(size_t)n * F4 + sub] = v;
    }
}

// -------- last GCN2Conv layer fused with GCNConv GEMM: y = relu(...)@Wg ---
__global__ void __launch_bounds__(256, 5)
k_layer_gcn(const float* __restrict__ x_in, float* __restrict__ y_out,
            const float* __restrict__ W, const float* __restrict__ Wg) {
    __shared__ float4 Wsh[F * F4];   // reused for W then Wg
    __shared__ float  hs[NPB][HPAD];
    int t = threadIdx.x;
    const float4* W4  = (const float4*)W;
    const float4* Wg4 = (const float4*)Wg;
#pragma unroll
    for (int i = 0; i < 4; i++) Wsh[t + i * 256] = W4[t + i * 256];
    __syncthreads();

    int warp = t >> 5, lane = t & 31, half = lane >> 4, sub = lane & 15;
    int nb = warp * 2 + half;
    int nbase = blockIdx.x * NPB;

    const float4* x4 = (const float4*)x_in;
#pragma unroll
    for (int r = 0; r < RND; r++) {
        int n = nbase + r * 16 + nb;
        int eb = __ldg(&g_rowptr[n]), ee = __ldg(&g_rowptr[n + 1]);
        float4 acc = gather_row(x4, eb, ee, sub);
        float dn = g_dinv[n];
        float4 xn = __ldg(&x4[(size_t)n * F4 + sub]);
        store_h(&hs[r * 16 + nb][0], sub, acc, xn, dn * dn);
    }
    __syncwarp(0xffffffffu);

    float4 o[RND];
#pragma unroll
    for (int r = 0; r < RND; r++) o[r] = make_float4(0.f, 0.f, 0.f, 0.f);
#pragma unroll
    for (int j = 0; j < 16; j++) {
        float4 w0 = Wsh[(4 * j + 0) * F4 + sub];
        float4 w1 = Wsh[(4 * j + 1) * F4 + sub];
        float4 w2 = Wsh[(4 * j + 2) * F4 + sub];
        float4 w3 = Wsh[(4 * j + 3) * F4 + sub];
#pragma unroll
        for (int r = 0; r < RND; r++) {
            float4 hv = ((const float4*)&hs[r * 16 + nb][0])[j];
            o[r].x = fmaf(hv.x, w0.x, o[r].x); o[r].y = fmaf(hv.x, w0.y, o[r].y);
            o[r].z = fmaf(hv.x, w0.z, o[r].z); o[r].w = fmaf(hv.x, w0.w, o[r].w);
            o[r].x = fmaf(hv.y, w1.x, o[r].x); o[r].y = fmaf(hv.y, w1.y, o[r].y);
            o[r].z = fmaf(hv.y, w1.z, o[r].z); o[r].w = fmaf(hv.y, w1.w, o[r].w);
            o[r].x = fmaf(hv.z, w2.x, o[r].x); o[r].y = fmaf(hv.z, w2.y, o[r].y);
            o[r].z = fmaf(hv.z, w2.z, o[r].z); o[r].w = fmaf(hv.z, w2.w, o[r].w);
            o[r].x = fmaf(hv.w, w3.x, o[r].x); o[r].y = fmaf(hv.w, w3.y, o[r].y);
            o[r].z = fmaf(hv.w, w3.z, o[r].z); o[r].w = fmaf(hv.w, w3.w, o[r].w);
        }
    }
    // relu, stash o back into hs; swap Wsh -> Wg; second GEMM
    __syncthreads();                          // everyone done reading Wsh & hs
#pragma unroll
    for (int r = 0; r < RND; r++) {
        float4 v;
        v.x = fmaxf(o[r].x, 0.f); v.y = fmaxf(o[r].y, 0.f);
        v.z = fmaxf(o[r].z, 0.f); v.w = fmaxf(o[r].w, 0.f);
        ((float4*)&hs[r * 16 + nb][0])[sub] = v;
    }
#pragma unroll
    for (int i = 0; i < 4; i++) Wsh[t + i * 256] = Wg4[t + i * 256];
    __syncthreads();

    float4 y[RND];
#pragma unroll
    for (int r = 0; r < RND; r++) y[r] = make_float4(0.f, 0.f, 0.f, 0.f);
#pragma unroll
    for (int j = 0; j < 16; j++) {
        float4 w0 = Wsh[(4 * j + 0) * F4 + sub];
        float4 w1 = Wsh[(4 * j + 1) * F4 + sub];
        float4 w2 = Wsh[(4 * j + 2) * F4 + sub];
        float4 w3 = Wsh[(4 * j + 3) * F4 + sub];
#pragma unroll
        for (int r = 0; r < RND; r++) {
            float4 hv = ((const float4*)&hs[r * 16 + nb][0])[j];
            y[r].x = fmaf(hv.x, w0.x, y[r].x); y[r].y = fmaf(hv.x, w0.y, y[r].y);
            y[r].z = fmaf(hv.x, w0.z, y[r].z); y[r].w = fmaf(hv.x, w0.w, y[r].w);
            y[r].x = fmaf(hv.y, w1.x, y[r].x); y[r].y = fmaf(hv.y, w1.y, y[r].y);
            y[r].z = fmaf(hv.y, w1.z, y[r].z); y[r].w = fmaf(hv.y, w1.w, y[r].w);
            y[r].x = fmaf(hv.z, w2.x, y[r].x); y[r].y = fmaf(hv.z, w2.y, y[r].y);
            y[r].z = fmaf(hv.z, w2.z, y[r].z); y[r].w = fmaf(hv.z, w2.w, y[r].w);
            y[r].x = fmaf(hv.w, w3.x, y[r].x); y[r].y = fmaf(hv.w, w3.y, y[r].y);
            y[r].z = fmaf(hv.w, w3.z, y[r].z); y[r].w = fmaf(hv.w, w3.w, y[r].w);
        }
    }
#pragma unroll
    for (int r = 0; r < RND; r++) {
        int n = nbase + r * 16 + nb;
        ((float4*)y_out)[(size_t)n * F4 + sub] = y[r];
    }
}

// ---------------- final: h = prop(y)+b_gcn ; out1 = h@W1+b1 ; out2 = h@W2+b2
__global__ void __launch_bounds__(256, 5)
k_final(const float* __restrict__ y, float* __restrict__ out,
        const float* __restrict__ W1, const float* __restrict__ b1,
        const float* __restrict__ W2, const float* __restrict__ b2,
        const float* __restrict__ bg) {
    __shared__ float W1s[F * C1];
    __shared__ float W2s[F * C2];
    __shared__ float bgs[F];
    int t = threadIdx.x;
    if (t < F * C1) W1s[t] = W1[t];
    if (t < F * C2) W2s[t] = W2[t];
    if (t < F)      bgs[t] = bg[t];
    __syncthreads();

    int warp = t >> 5, lane = t & 31, half = lane >> 4, sub = lane & 15;
    int nb = warp * 2 + half;
    int n  = blockIdx.x * 16 + nb;

    const float4* y4 = (const float4*)y;
    int eb = __ldg(&g_rowptr[n]), ee = __ldg(&g_rowptr[n + 1]);
    float4 acc = gather_row(y4, eb, ee, sub);

    float dn = g_dinv[n];
    float sn = dn * dn;
    float4 yn = __ldg(&y4[(size_t)n * F4 + sub]);
    float4 h;
    h.x = acc.x + sn * yn.x + bgs[4 * sub + 0];
    h.y = acc.y + sn * yn.y + bgs[4 * sub + 1];
    h.z = acc.z + sn * yn.z + bgs[4 * sub + 2];
    h.w = acc.w + sn * yn.w + bgs[4 * sub + 3];

    // write h (third output block)
    float* out_h = out + (size_t)NN * (C1 + C2);
    ((float4*)out_h)[(size_t)n * F4 + sub] = h;

    // heads: per-lane partials over its 4 features, reduce across 16 lanes
    float p[C1 + C2];
#pragma unroll
    for (int c = 0; c < C1; c++)
        p[c] = h.x * W1s[(4 * sub + 0) * C1 + c] + h.y * W1s[(4 * sub + 1) * C1 + c]
             + h.z * W1s[(4 * sub + 2) * C1 + c] + h.w * W1s[(4 * sub + 3) * C1 + c];
#pragma unroll
    for (int c = 0; c < C2; c++)
        p[C1 + c] = h.x * W2s[(4 * sub + 0) * C2 + c] + h.y * W2s[(4 * sub + 1) * C2 + c]
                  + h.z * W2s[(4 * sub + 2) * C2 + c] + h.w * W2s[(4 * sub + 3) * C2 + c];
#pragma unroll
    for (int off = 8; off; off >>= 1) {
#pragma unroll
        for (int c = 0; c < C1 + C2; c++)
            p[c] += __shfl_down_sync(0xffffffffu, p[c], off, 16);
    }
    if (sub == 0) {
#pragma unroll
        for (int c = 0; c < C1; c++)
            out[(size_t)n * C1 + c] = p[c] + __ldg(&b1[c]);
        float* o2 = out + (size_t)NN * C1;
#pragma unroll
        for (int c = 0; c < C2; c++)
            o2[(size_t)n * C2 + c] = p[C1 + c] + __ldg(&b2[c]);
    }
}

// ---------------- launch ----------------
extern "C" void kernel_launch(void* const* d_in, const int* in_sizes, int n_in,
                              void* d_out, int out_size) {
    const float* x   = (const float*)d_in[0];
    const int*   ei  = (const int*)  d_in[1];
    const float* Ws  = (const float*)d_in[2];
    const float* Wg  = (const float*)d_in[3];
    const float* bg  = (const float*)d_in[4];
    const float* W1  = (const float*)d_in[5];
    const float* b1  = (const float*)d_in[6];
    const float* W2  = (const float*)d_in[7];
    const float* b2  = (const float*)d_in[8];
    float* out = (float*)d_out;

    float *xa, *xb;
    cudaGetSymbolAddress((void**)&xa, g_xa);
    cudaGetSymbolAddress((void**)&xb, g_xb);

    int ebq = (EE / 4 + 255) / 256;                   // 977
    k_hist<<<ebq, 256>>>(ei + EE);                    // launch 0
    k_scan<<<1, 1024>>>();                            // launch 1 (re-zeroes cnt)
    k_scatter<<<ebq, 256>>>(ei);                      // launch 2

    int gb = NN / NPB;                                // 1250, exact
    k_layer    <<<gb, 256>>>(x,  xa, Ws);             // launch 3  <- ncu lands here
    k_layer    <<<gb, 256>>>(xa, xb, Ws + F * F);     // launch 4
    k_layer_gcn<<<gb, 256>>>(xb, xa, Ws + 2 * F * F, Wg);
    k_final    <<<NN / 16, 256>>>(xa, out, W1, b1, W2, b2, bg);
}